// round 5
// baseline (speedup 1.0000x reference)
#include <cuda_runtime.h>
#include <cstdint>

#define RES 256
#define N_TOTAL (8 * 65536)
#define NBINS 32768          // 32x32x32 bins of 8^3 voxels

__device__ int   g_hist[NBINS];
__device__ float4 g_payload[N_TOTAL];   // (gx, gy, gz, idx-as-float-bits)

__device__ __forceinline__ int bin_of(float gx, float gy, float gz) {
    // ix = 256*gx + 127.5 (EXTENT=0.5 fold); bin coord = clamp(floor(ix),0,255)>>3
    int bx = min(max((int)floorf(fmaf(gx, 256.0f, 127.5f)), 0), 255) >> 3;
    int by = min(max((int)floorf(fmaf(gy, 256.0f, 127.5f)), 0), 255) >> 3;
    int bz = min(max((int)floorf(fmaf(gz, 256.0f, 127.5f)), 0), 255) >> 3;
    return (bz << 10) | (by << 5) | bx;   // x-fastest: adjacent bins share rows
}

// ---------------- K0: zero histogram ----------------
__global__ void k_zero() {
    int i = blockIdx.x * blockDim.x + threadIdx.x;
    if (i < NBINS) g_hist[i] = 0;
}

// ---------------- K1: histogram ----------------
__global__ __launch_bounds__(256) void k_hist(const float* __restrict__ x) {
    int i = blockIdx.x * blockDim.x + threadIdx.x;
    if (i >= N_TOTAL) return;
    float gx = __ldcs(x + 3 * i + 0);
    float gy = __ldcs(x + 3 * i + 1);
    float gz = __ldcs(x + 3 * i + 2);
    atomicAdd(&g_hist[bin_of(gx, gy, gz)], 1);
}

// ---------------- K2: exclusive scan (single block) ----------------
__global__ __launch_bounds__(1024) void k_scan() {
    __shared__ int part[1024];
    int t = threadIdx.x;
    // each thread owns 32 consecutive bins, loaded as 8 x int4
    int4 v[8];
    int sum = 0;
    const int4* hp = (const int4*)(g_hist) + t * 8;
    #pragma unroll
    for (int k = 0; k < 8; k++) {
        v[k] = hp[k];
        sum += v[k].x + v[k].y + v[k].z + v[k].w;
    }
    part[t] = sum;
    __syncthreads();
    // Hillis-Steele inclusive scan over 1024 partials
    #pragma unroll
    for (int off = 1; off < 1024; off <<= 1) {
        int val = (t >= off) ? part[t - off] : 0;
        __syncthreads();
        part[t] += val;
        __syncthreads();
    }
    int run = part[t] - sum;  // exclusive prefix for this thread's chunk
    int4* wp = (int4*)(g_hist) + t * 8;
    #pragma unroll
    for (int k = 0; k < 8; k++) {
        int a = run;              run += v[k].x;
        int b = run;              run += v[k].y;
        int c = run;              run += v[k].z;
        int d = run;              run += v[k].w;
        wp[k] = make_int4(a, b, c, d);
    }
}

// ---------------- K3: scatter into sorted payload ----------------
__global__ __launch_bounds__(256) void k_scatter(const float* __restrict__ x) {
    int i = blockIdx.x * blockDim.x + threadIdx.x;
    if (i >= N_TOTAL) return;
    float gx = __ldcs(x + 3 * i + 0);
    float gy = __ldcs(x + 3 * i + 1);
    float gz = __ldcs(x + 3 * i + 2);
    int pos = atomicAdd(&g_hist[bin_of(gx, gy, gz)], 1);
    float4 p = make_float4(gx, gy, gz, __int_as_float(i));
    g_payload[pos] = p;
}

// ---------------- K4: sorted trilinear gather ----------------
__device__ __forceinline__ uint64_t evict_last_policy() {
    uint64_t pol;
    asm("createpolicy.fractional.L2::evict_last.b64 %0, 1.0;" : "=l"(pol));
    return pol;
}
__device__ __forceinline__ float4 ldg_keep4(const float* p, uint64_t pol) {
    float4 v;
    asm volatile("ld.global.nc.L2::cache_hint.v4.f32 {%0,%1,%2,%3}, [%4], %5;"
                 : "=f"(v.x), "=f"(v.y), "=f"(v.z), "=f"(v.w)
                 : "l"(p), "l"(pol));
    return v;
}
__device__ __forceinline__ float ldg_keep(const float* p, uint64_t pol) {
    float v;
    asm volatile("ld.global.nc.L2::cache_hint.f32 %0, [%1], %2;"
                 : "=f"(v) : "l"(p), "l"(pol));
    return v;
}
__device__ __forceinline__ float sel4(float4 v, int o) {
    float r = (o == 1) ? v.y : v.x;
    r = (o == 2) ? v.z : r;
    r = (o == 3) ? v.w : r;
    return r;
}

__global__ __launch_bounds__(256) void k_gather(
    const float* __restrict__ vol,
    float* __restrict__ out)
{
    int j = blockIdx.x * blockDim.x + threadIdx.x;
    if (j >= N_TOTAL) return;

    uint64_t pol = evict_last_policy();

    float4 p = __ldcs((const float4*)g_payload + j);
    float gx = p.x, gy = p.y, gz = p.z;
    int   oi = __float_as_int(p.w);

    float ix = fmaf(gx, 256.0f, 127.5f);
    float iy = fmaf(gy, 256.0f, 127.5f);
    float iz = fmaf(gz, 256.0f, 127.5f);

    float fx0 = floorf(ix), fy0 = floorf(iy), fz0 = floorf(iz);
    float tx = ix - fx0, ty = iy - fy0, tz = iz - fz0;

    int x0 = (int)fx0, y0 = (int)fy0, z0 = (int)fz0;
    int x1 = x0 + 1,   y1 = y0 + 1,   z1 = z0 + 1;

    bool vx0 = (x0 >= 0) & (x0 < RES);
    bool vx1 = (x1 >= 0) & (x1 < RES);
    bool vy0 = (y0 >= 0) & (y0 < RES);
    bool vy1 = (y1 >= 0) & (y1 < RES);
    bool vz0 = (z0 >= 0) & (z0 < RES);
    bool vz1 = (z1 >= 0) & (z1 < RES);

    int cx0 = min(max(x0, 0), RES - 1);
    int cx1 = min(max(x1, 0), RES - 1);
    int cy0 = min(max(y0, 0), RES - 1);
    int cy1 = min(max(y1, 0), RES - 1);
    int cz0 = min(max(z0, 0), RES - 1);
    int cz1 = min(max(z1, 0), RES - 1);

    long pz0 = (long)cz0 * (RES * RES);
    long pz1 = (long)cz1 * (RES * RES);
    long r00 = pz0 + cy0 * RES;
    long r01 = pz0 + cy1 * RES;
    long r10 = pz1 + cy0 * RES;
    long r11 = pz1 + cy1 * RES;

    int base = cx0 & ~3;
    int ao = cx0 - base;
    int d1 = cx1 - base;
    int bo = min(d1, 3);
    bool need_extra = (d1 == 4);

    float4 q00 = ldg_keep4(vol + r00 + base, pol);
    float4 q01 = ldg_keep4(vol + r01 + base, pol);
    float4 q10 = ldg_keep4(vol + r10 + base, pol);
    float4 q11 = ldg_keep4(vol + r11 + base, pol);

    float e00 = 0.f, e01 = 0.f, e10 = 0.f, e11 = 0.f;
    if (need_extra) {
        e00 = ldg_keep(vol + r00 + cx1, pol);
        e01 = ldg_keep(vol + r01 + cx1, pol);
        e10 = ldg_keep(vol + r10 + cx1, pol);
        e11 = ldg_keep(vol + r11 + cx1, pol);
    }

    float a00 = sel4(q00, ao), a01 = sel4(q01, ao);
    float a10 = sel4(q10, ao), a11 = sel4(q11, ao);
    float b00 = need_extra ? e00 : sel4(q00, bo);
    float b01 = need_extra ? e01 : sel4(q01, bo);
    float b10 = need_extra ? e10 : sel4(q10, bo);
    float b11 = need_extra ? e11 : sel4(q11, bo);

    a00 = (vz0 & vy0 & vx0) ? a00 : 0.0f;
    b00 = (vz0 & vy0 & vx1) ? b00 : 0.0f;
    a01 = (vz0 & vy1 & vx0) ? a01 : 0.0f;
    b01 = (vz0 & vy1 & vx1) ? b01 : 0.0f;
    a10 = (vz1 & vy0 & vx0) ? a10 : 0.0f;
    b10 = (vz1 & vy0 & vx1) ? b10 : 0.0f;
    a11 = (vz1 & vy1 & vx0) ? a11 : 0.0f;
    b11 = (vz1 & vy1 & vx1) ? b11 : 0.0f;

    float c00 = fmaf(tx, b00 - a00, a00);
    float c01 = fmaf(tx, b01 - a01, a01);
    float c10 = fmaf(tx, b10 - a10, a10);
    float c11 = fmaf(tx, b11 - a11, a11);

    float c0 = fmaf(ty, c01 - c00, c00);
    float c1 = fmaf(ty, c11 - c10, c10);
    float c  = fmaf(tz, c1 - c0, c0);

    float r = 100.0f * c;
    asm volatile("st.global.cs.f32 [%0], %1;" :: "l"(out + oi), "f"(r) : "memory");
}

extern "C" void kernel_launch(void* const* d_in, const int* in_sizes, int n_in,
                              void* d_out, int out_size)
{
    const float* x   = (const float*)d_in[0];  // [8, 65536, 3] f32
    const float* vol = (const float*)d_in[1];  // [256,256,256] f32
    float* out = (float*)d_out;                // [8, 65536] f32

    int threads = 256;
    int blocks  = (N_TOTAL + threads - 1) / threads;

    k_zero<<<(NBINS + 255) / 256, 256>>>();
    k_hist<<<blocks, threads>>>(x);
    k_scan<<<1, 1024>>>();
    k_scatter<<<blocks, threads>>>(x);
    k_gather<<<blocks, threads>>>(vol, out);
}

// round 6
// speedup vs baseline: 2.6388x; 2.6388x over previous
#include <cuda_runtime.h>
#include <cstdint>

#define RES 256
#define N_TOTAL (8 * 65536)

__device__ __forceinline__ uint64_t evict_last_policy() {
    uint64_t pol;
    asm("createpolicy.fractional.L2::evict_last.b64 %0, 1.0;" : "=l"(pol));
    return pol;
}

struct F8 { float v[8]; };

// 256-bit load: one 32B sector exactly (p must be 32B aligned)
__device__ __forceinline__ F8 ldg_keep8(const float* p, uint64_t pol) {
    F8 r;
    asm volatile("ld.global.nc.L2::cache_hint.v8.b32 {%0,%1,%2,%3,%4,%5,%6,%7}, [%8], %9;"
                 : "=f"(r.v[0]), "=f"(r.v[1]), "=f"(r.v[2]), "=f"(r.v[3]),
                   "=f"(r.v[4]), "=f"(r.v[5]), "=f"(r.v[6]), "=f"(r.v[7])
                 : "l"(p), "l"(pol));
    return r;
}

__device__ __forceinline__ float ldg_keep(const float* p, uint64_t pol) {
    float v;
    asm volatile("ld.global.nc.L2::cache_hint.f32 %0, [%1], %2;"
                 : "=f"(v) : "l"(p), "l"(pol));
    return v;
}

__device__ __forceinline__ float sel8(const F8& q, int o) {
    // o in 0..7
    float lo = (o & 1) ? q.v[1] : q.v[0];
    lo = ((o & 3) == 2) ? q.v[2] : lo;
    lo = ((o & 3) == 3) ? q.v[3] : lo;
    float hi = (o & 1) ? q.v[5] : q.v[4];
    hi = ((o & 3) == 2) ? q.v[6] : hi;
    hi = ((o & 3) == 3) ? q.v[7] : hi;
    return (o >= 4) ? hi : lo;
}

__global__ __launch_bounds__(256) void volume_sample_kernel(
    const float* __restrict__ x,
    const float* __restrict__ vol,
    float* __restrict__ out)
{
    int i = blockIdx.x * blockDim.x + threadIdx.x;
    if (i >= N_TOTAL) return;

    uint64_t pol = evict_last_policy();

    // EXTENT=0.5 fold: ix = 256*gx + 127.5
    float gx = __ldcs(x + 3 * i + 0);
    float gy = __ldcs(x + 3 * i + 1);
    float gz = __ldcs(x + 3 * i + 2);

    float ix = fmaf(gx, 256.0f, 127.5f);
    float iy = fmaf(gy, 256.0f, 127.5f);
    float iz = fmaf(gz, 256.0f, 127.5f);

    float fx0 = floorf(ix), fy0 = floorf(iy), fz0 = floorf(iz);
    float tx = ix - fx0, ty = iy - fy0, tz = iz - fz0;

    int x0 = (int)fx0, y0 = (int)fy0, z0 = (int)fz0;
    int x1 = x0 + 1,   y1 = y0 + 1,   z1 = z0 + 1;

    bool vx0 = (x0 >= 0) & (x0 < RES);
    bool vx1 = (x1 >= 0) & (x1 < RES);
    bool vy0 = (y0 >= 0) & (y0 < RES);
    bool vy1 = (y1 >= 0) & (y1 < RES);
    bool vz0 = (z0 >= 0) & (z0 < RES);
    bool vz1 = (z1 >= 0) & (z1 < RES);

    int cx0 = min(max(x0, 0), RES - 1);
    int cx1 = min(max(x1, 0), RES - 1);
    int cy0 = min(max(y0, 0), RES - 1);
    int cy1 = min(max(y1, 0), RES - 1);
    int cz0 = min(max(z0, 0), RES - 1);
    int cz1 = min(max(z1, 0), RES - 1);

    long pz0 = (long)cz0 * (RES * RES);
    long pz1 = (long)cz1 * (RES * RES);
    long r00 = pz0 + cy0 * RES;   // (z0, y0)
    long r01 = pz0 + cy1 * RES;   // (z0, y1)
    long r10 = pz1 + cy0 * RES;   // (z1, y0)
    long r11 = pz1 + cy1 * RES;   // (z1, y1)

    int base = cx0 & ~7;          // 32B aligned; base+7 <= 255 always
    int ao = cx0 - base;          // 0..7
    int d1 = cx1 - base;          // 0..8
    int bo = min(d1, 7);
    bool need_extra = (d1 == 8);  // only cx0%8==7 with valid x1 (~12.5%)

    // 4 single-sector gathers, one per (z,y) row
    F8 q00 = ldg_keep8(vol + r00 + base, pol);
    F8 q01 = ldg_keep8(vol + r01 + base, pol);
    F8 q10 = ldg_keep8(vol + r10 + base, pol);
    F8 q11 = ldg_keep8(vol + r11 + base, pol);

    float e00 = 0.f, e01 = 0.f, e10 = 0.f, e11 = 0.f;
    if (need_extra) {
        e00 = ldg_keep(vol + r00 + cx1, pol);
        e01 = ldg_keep(vol + r01 + cx1, pol);
        e10 = ldg_keep(vol + r10 + cx1, pol);
        e11 = ldg_keep(vol + r11 + cx1, pol);
    }

    float a00 = sel8(q00, ao), a01 = sel8(q01, ao);
    float a10 = sel8(q10, ao), a11 = sel8(q11, ao);
    float b00 = need_extra ? e00 : sel8(q00, bo);
    float b01 = need_extra ? e01 : sel8(q01, bo);
    float b10 = need_extra ? e10 : sel8(q10, bo);
    float b11 = need_extra ? e11 : sel8(q11, bo);

    a00 = (vz0 & vy0 & vx0) ? a00 : 0.0f;
    b00 = (vz0 & vy0 & vx1) ? b00 : 0.0f;
    a01 = (vz0 & vy1 & vx0) ? a01 : 0.0f;
    b01 = (vz0 & vy1 & vx1) ? b01 : 0.0f;
    a10 = (vz1 & vy0 & vx0) ? a10 : 0.0f;
    b10 = (vz1 & vy0 & vx1) ? b10 : 0.0f;
    a11 = (vz1 & vy1 & vx0) ? a11 : 0.0f;
    b11 = (vz1 & vy1 & vx1) ? b11 : 0.0f;

    float c00 = fmaf(tx, b00 - a00, a00);
    float c01 = fmaf(tx, b01 - a01, a01);
    float c10 = fmaf(tx, b10 - a10, a10);
    float c11 = fmaf(tx, b11 - a11, a11);

    float c0 = fmaf(ty, c01 - c00, c00);
    float c1 = fmaf(ty, c11 - c10, c10);
    float c  = fmaf(tz, c1 - c0, c0);

    float r = 100.0f * c;
    asm volatile("st.global.cs.f32 [%0], %1;" :: "l"(out + i), "f"(r) : "memory");
}

extern "C" void kernel_launch(void* const* d_in, const int* in_sizes, int n_in,
                              void* d_out, int out_size)
{
    const float* x   = (const float*)d_in[0];  // [8, 65536, 3] f32
    const float* vol = (const float*)d_in[1];  // [256,256,256] f32
    float* out = (float*)d_out;                // [8, 65536] f32

    int threads = 256;
    int blocks  = (N_TOTAL + threads - 1) / threads;
    volume_sample_kernel<<<blocks, threads>>>(x, vol, out);
}